// round 13
// baseline (speedup 1.0000x reference)
#include <cuda_runtime.h>
#include <cuda_bf16.h>
#include <math.h>

#define Bb 2
#define Tt 1024
#define Cc 2048
#define Hh 16
#define Dd 128
#define BT (Bb*Tt)

typedef unsigned long long u64;
typedef unsigned int u32;

// ================= portable tensor-core helpers ===================================
__device__ __forceinline__ u32 smem_u32_of(const void* p) {
    u32 a; asm("{ .reg .u64 t; cvta.to.shared.u64 t, %1; cvt.u32.u64 %0, t; }"
               : "=r"(a) : "l"(p));
    return a;
}
__device__ __forceinline__ void ldsm_x4(u32& r0, u32& r1, u32& r2, u32& r3, u32 addr) {
    asm volatile("ldmatrix.sync.aligned.m8n8.x4.shared.b16 {%0,%1,%2,%3}, [%4];"
                 : "=r"(r0), "=r"(r1), "=r"(r2), "=r"(r3) : "r"(addr));
}
__device__ __forceinline__ void mma16816(float* c, const u32* a, const u32* b) {
    asm volatile(
        "mma.sync.aligned.m16n8k16.row.col.f32.bf16.bf16.f32 "
        "{%0,%1,%2,%3}, {%4,%5,%6,%7}, {%8,%9}, {%0,%1,%2,%3};"
        : "+f"(c[0]), "+f"(c[1]), "+f"(c[2]), "+f"(c[3])
        : "r"(a[0]), "r"(a[1]), "r"(a[2]), "r"(a[3]), "r"(b[0]), "r"(b[1]));
}
__device__ __forceinline__ u32 pack_bf2(__nv_bfloat16 x, __nv_bfloat16 y) {
    __nv_bfloat162 t; t.x = x; t.y = y;
    return *(u32*)&t;
}
__device__ __forceinline__ u32 split2(float x, float y, u32& lo) {
    __nv_bfloat16 hx = __float2bfloat16(x);
    __nv_bfloat16 hy = __float2bfloat16(y);
    lo = pack_bf2(__float2bfloat16(x - __bfloat162float(hx)),
                  __float2bfloat16(y - __bfloat162float(hy)));
    return pack_bf2(hx, hy);
}
__device__ __forceinline__ void cp16(u32 smem, const void* g) {
    asm volatile("cp.async.cg.shared.global [%0], [%1], 16;" :: "r"(smem), "l"(g));
}
#define CP_COMMIT() asm volatile("cp.async.commit_group;" ::: "memory")
#define CP_WAIT(n)  asm volatile("cp.async.wait_group %0;" :: "n"(n) : "memory")

// ================= scratch ========================================================
__device__ float g_q[BT * Cc];
__device__ float g_k[BT * Cc];
__device__ float g_v[BT * Cc];
__device__ float g_cos[Tt * 64];
__device__ float g_sin[Tt * 64];
__device__ __nv_bfloat16 g_xh[BT * Cc],  g_xl[BT * Cc];
__device__ __nv_bfloat16 g_wqh[Cc * Cc], g_wql[Cc * Cc];
__device__ __nv_bfloat16 g_wkh[Cc * Cc], g_wkl[Cc * Cc];
__device__ __nv_bfloat16 g_wvh[Cc * Cc], g_wvl[Cc * Cc];
__device__ __nv_bfloat16 g_woh[Cc * Cc], g_wol[Cc * Cc];
__device__ __nv_bfloat16 g_yh[BT * Cc],  g_yl[BT * Cc];
__device__ __nv_bfloat16 g_qhb[BT * Cc], g_qlb[BT * Cc];
__device__ __nv_bfloat16 g_khb[BT * Cc], g_klb[BT * Cc];
__device__ __nv_bfloat16 g_vth[32 * 128 * Tt], g_vtl[32 * 128 * Tt];

// ================= fp32 -> bf16 hi/lo split ======================================
__device__ __forceinline__ void split_store4(const float* src, __nv_bfloat16* hi,
                                             __nv_bfloat16* lo, int i)
{
    float4 v = *(const float4*)(src + i);
    __nv_bfloat16 h0 = __float2bfloat16(v.x);
    __nv_bfloat16 h1 = __float2bfloat16(v.y);
    __nv_bfloat16 h2 = __float2bfloat16(v.z);
    __nv_bfloat16 h3 = __float2bfloat16(v.w);
    __nv_bfloat162 H0; H0.x = h0; H0.y = h1;
    __nv_bfloat162 H1; H1.x = h2; H1.y = h3;
    *(__nv_bfloat162*)(hi + i)     = H0;
    *(__nv_bfloat162*)(hi + i + 2) = H1;
    __nv_bfloat162 L0, L1;
    L0.x = __float2bfloat16(v.x - __bfloat162float(h0));
    L0.y = __float2bfloat16(v.y - __bfloat162float(h1));
    L1.x = __float2bfloat16(v.z - __bfloat162float(h2));
    L1.y = __float2bfloat16(v.w - __bfloat162float(h3));
    *(__nv_bfloat162*)(lo + i)     = L0;
    *(__nv_bfloat162*)(lo + i + 2) = L1;
}

__global__ void __launch_bounds__(256)
conv_split(const float* __restrict__ src, __nv_bfloat16* __restrict__ hi,
           __nv_bfloat16* __restrict__ lo)
{
    int i = (blockIdx.x * blockDim.x + threadIdx.x) * 4;
    split_store4(src, hi, lo, i);
}

__global__ void __launch_bounds__(256)
conv_split2(const float* __restrict__ s0, __nv_bfloat16* __restrict__ h0,
            __nv_bfloat16* __restrict__ l0, const float* __restrict__ s1,
            __nv_bfloat16* __restrict__ h1, __nv_bfloat16* __restrict__ l1)
{
    int i = (blockIdx.x * blockDim.x + threadIdx.x) * 4;
    if (blockIdx.z == 0) split_store4(s0, h0, l0, i);
    else                 split_store4(s1, h1, l1, i);
}

// ================= HMMA split-bf16 NT GEMM, cp.async 3-stage, 2 CTAs/SM ===========
// CTA tile 128x64, warp tile 32x32, BK=32. Stage: Ah/Al 128x32 + Bh/Bl 64x32,
// rows padded to 80 B.
#define SRB 80                               // bytes per padded row
#define AH_O 0
#define AL_O (128 * SRB)                     // 10240
#define BH_O (2 * 128 * SRB)                 // 20480
#define BL_O (BH_O + 64 * SRB)               // 25600
#define STGB (BL_O + 64 * SRB)               // 30720
#define NSTG 3
#define GEMM_SMEM (NSTG * STGB)              // 92160

__device__ __forceinline__ void gemm_load_chunk(
    u32 sb32, const __nv_bfloat16* Ah, const __nv_bfloat16* Al,
    const __nv_bfloat16* Bh, const __nv_bfloat16* Bl,
    int bm, int bn, int ch, int tid)
{
    const int k0 = ch * 32;
    const u32 st = sb32 + (u32)(ch % NSTG) * STGB;
#pragma unroll
    for (int m = 0; m < 2; m++) {
        int idx = tid * 2 + m;               // 0..511
        int row = idx >> 2, seg = idx & 3;
        u32 so = (u32)(row * SRB + seg * 16);
        size_t go = (size_t)(bm + row) * 2048 + k0 + seg * 8;
        cp16(st + AH_O + so, Ah + go);
        cp16(st + AL_O + so, Al + go);
    }
    {
        int row = tid >> 2, seg = tid & 3;   // 64 rows x 4 segs = 256
        u32 so = (u32)(row * SRB + seg * 16);
        size_t go = (size_t)(bn + row) * 2048 + k0 + seg * 8;
        cp16(st + BH_O + so, Bh + go);
        cp16(st + BL_O + so, Bl + go);
    }
    CP_COMMIT();
}

__device__ __forceinline__ void mma_gemm_body(
    const __nv_bfloat16* __restrict__ Ah, const __nv_bfloat16* __restrict__ Al,
    const __nv_bfloat16* __restrict__ Bh, const __nv_bfloat16* __restrict__ Bl,
    float* __restrict__ Cout)
{
    extern __shared__ char sb[];
    const u32 sb32 = smem_u32_of(sb);

    const int tid = threadIdx.x;
    const int wid = tid >> 5;
    const int lane = tid & 31;
    const int bm = blockIdx.y * 128;
    const int bn = blockIdx.x * 64;
    const int m0 = (wid >> 1) * 32;
    const int n0 = (wid & 1) * 32;

    const u32 aRow = (u32)((lane & 7) + ((lane >> 3) & 1) * 8);
    const u32 aCol = (u32)(((lane >> 4) & 1) * 16);
    const u32 bRow = (u32)((lane & 7) + ((lane >> 4) & 1) * 8);
    const u32 bCol = (u32)(((lane >> 3) & 1) * 16);

    float c[2][4][4];
#pragma unroll
    for (int i = 0; i < 2; i++)
#pragma unroll
        for (int j = 0; j < 4; j++)
#pragma unroll
            for (int q = 0; q < 4; q++) c[i][j][q] = 0.f;

    // prologue: stages 0..NSTG-2
    gemm_load_chunk(sb32, Ah, Al, Bh, Bl, bm, bn, 0, tid);
    gemm_load_chunk(sb32, Ah, Al, Bh, Bl, bm, bn, 1, tid);

    for (int ch = 0; ch < 64; ch++) {
        CP_WAIT(NSTG - 2);
        __syncthreads();

        if (ch + NSTG - 1 < 64)
            gemm_load_chunk(sb32, Ah, Al, Bh, Bl, bm, bn, ch + NSTG - 1, tid);
        else
            CP_COMMIT();                      // keep group accounting aligned

        const u32 base = sb32 + (u32)(ch % NSTG) * STGB;
#pragma unroll
        for (int s = 0; s < 2; s++) {
            const u32 kb = (u32)(s * 32);
            u32 ah[2][4], al[2][4], bh[2][4], bl[2][4];
#pragma unroll
            for (int mi = 0; mi < 2; mi++) {
                u32 ra = (u32)(m0 + mi * 16 + aRow) * SRB + kb + aCol;
                ldsm_x4(ah[mi][0], ah[mi][1], ah[mi][2], ah[mi][3], base + AH_O + ra);
                ldsm_x4(al[mi][0], al[mi][1], al[mi][2], al[mi][3], base + AL_O + ra);
            }
#pragma unroll
            for (int np = 0; np < 2; np++) {
                u32 rb = (u32)(n0 + np * 16 + bRow) * SRB + kb + bCol;
                ldsm_x4(bh[np][0], bh[np][1], bh[np][2], bh[np][3], base + BH_O + rb);
                ldsm_x4(bl[np][0], bl[np][1], bl[np][2], bl[np][3], base + BL_O + rb);
            }
#pragma unroll
            for (int mi = 0; mi < 2; mi++)
#pragma unroll
                for (int np = 0; np < 2; np++) {
                    mma16816(c[mi][np * 2 + 0], ah[mi], &bh[np][0]);
                    mma16816(c[mi][np * 2 + 1], ah[mi], &bh[np][2]);
                    mma16816(c[mi][np * 2 + 0], al[mi], &bh[np][0]);
                    mma16816(c[mi][np * 2 + 1], al[mi], &bh[np][2]);
                    mma16816(c[mi][np * 2 + 0], ah[mi], &bl[np][0]);
                    mma16816(c[mi][np * 2 + 1], ah[mi], &bl[np][2]);
                }
        }
        __syncthreads();
    }

    const int g  = lane >> 2;
    const int tg = (lane & 3) * 2;
#pragma unroll
    for (int mi = 0; mi < 2; mi++)
#pragma unroll
        for (int nj = 0; nj < 4; nj++) {
            int row = bm + m0 + mi * 16 + g;
            int col = bn + n0 + nj * 8 + tg;
            float* cp0 = Cout + (size_t)row * 2048 + col;
            float* cp1 = Cout + (size_t)(row + 8) * 2048 + col;
            *(float2*)cp0 = make_float2(c[mi][nj][0], c[mi][nj][1]);
            *(float2*)cp1 = make_float2(c[mi][nj][2], c[mi][nj][3]);
        }
}

__global__ void __launch_bounds__(256, 2)
qkv_mma()
{
    const __nv_bfloat16 *Bh, *Bl; float* out;
    if (blockIdx.z == 0)      { Bh = g_wqh; Bl = g_wql; out = g_q; }
    else if (blockIdx.z == 1) { Bh = g_wkh; Bl = g_wkl; out = g_k; }
    else                      { Bh = g_wvh; Bl = g_wvl; out = g_v; }
    mma_gemm_body(g_xh, g_xl, Bh, Bl, out);
}

__global__ void __launch_bounds__(256, 2)
out_mma(float* __restrict__ out)
{
    mma_gemm_body(g_yh, g_yl, g_woh, g_wol, out);
}

// ================= RoPE cos/sin table =============================================
__global__ void cs_table_kernel()
{
    int idx = blockIdx.x * blockDim.x + threadIdx.x;
    if (idx >= Tt * 64) return;
    int t = idx >> 6;
    int j = idx & 63;
    float invf = (float)exp(-((double)(2 * j) / 128.0) * log(10000.0));
    float thf  = (float)t * invf;
    double cd, sd;
    sincos((double)thf, &cd, &sd);
    g_cos[idx] = (float)cd;
    g_sin[idx] = (float)sd;
}

// ================= prep: rope q/k -> bf16 splits ==================================
__global__ void __launch_bounds__(256)
prep_qk()
{
    int idx = blockIdx.x * blockDim.x + threadIdx.x;
    int j   = idx & 63;
    int h   = (idx >> 6) & 15;
    int row = idx >> 10;
    int t   = row & (Tt - 1);
    const float scale = 0.08838834764831845f;

    float c = g_cos[t * 64 + j];
    float s = g_sin[t * 64 + j];
    size_t base = (size_t)row * 2048 + (size_t)h * 128 + j;

    {
        float a0 = g_q[base], a1 = g_q[base + 64];
        float r0 = (a0 * c + a1 * s) * scale;
        float r1 = (a1 * c - a0 * s) * scale;
        __nv_bfloat16 h0 = __float2bfloat16(r0);
        __nv_bfloat16 h1 = __float2bfloat16(r1);
        g_qhb[base]      = h0;
        g_qhb[base + 64] = h1;
        g_qlb[base]      = __float2bfloat16(r0 - __bfloat162float(h0));
        g_qlb[base + 64] = __float2bfloat16(r1 - __bfloat162float(h1));
    }
    {
        float a0 = g_k[base], a1 = g_k[base + 64];
        float r0 = a0 * c + a1 * s;
        float r1 = a1 * c - a0 * s;
        __nv_bfloat16 h0 = __float2bfloat16(r0);
        __nv_bfloat16 h1 = __float2bfloat16(r1);
        g_khb[base]      = h0;
        g_khb[base + 64] = h1;
        g_klb[base]      = __float2bfloat16(r0 - __bfloat162float(h0));
        g_klb[base + 64] = __float2bfloat16(r1 - __bfloat162float(h1));
    }
}

// ================= prep: transpose V -> [bh][d=128][t] bf16 splits ================
__global__ void __launch_bounds__(256)
prep_vt()
{
    __shared__ float vs[128][65];
    const int tid = threadIdx.x;
    const int tt = blockIdx.x;
    const int bh = blockIdx.y;
    const int b = bh >> 4, h = bh & 15;
    const int tb = tt * 64;

    const float* vp = g_v + (size_t)b * Tt * Cc + (size_t)h * Dd;
    for (int e = tid; e < 64 * 128; e += 256) {
        int t = e >> 7, d = e & 127;
        vs[d][t] = vp[(size_t)(tb + t) * 2048 + d];
    }
    __syncthreads();

    __nv_bfloat16* oh = g_vth + (size_t)bh * 128 * Tt + tb;
    __nv_bfloat16* ol = g_vtl + (size_t)bh * 128 * Tt + tb;
    for (int e = tid; e < 128 * 32; e += 256) {
        int d = e >> 5, tw = (e & 31) * 2;
        float v0 = vs[d][tw], v1 = vs[d][tw + 1];
        u32 lo;
        u32 hi = split2(v0, v1, lo);
        *(u32*)(oh + (size_t)d * Tt + tw) = hi;
        *(u32*)(ol + (size_t)d * Tt + tw) = lo;
    }
}

// ================= HMMA flash attention (unchanged from R12) ======================
#define QROW 136
#define VROW 72
#define QH_OFF 0
#define QL_OFF (128 * QROW * 2)
#define KH_OFF 0
#define KL_OFF (64 * QROW * 2)
#define VTH_OFF (2 * 64 * QROW * 2)
#define VTL_OFF (VTH_OFF + 128 * VROW * 2)
#define FA_SMEM (VTL_OFF + 128 * VROW * 2)

__global__ void __launch_bounds__(256, 1)
flash_mma()
{
    extern __shared__ char sb[];
    const u32 sb32 = smem_u32_of(sb);

    const int tid = threadIdx.x;
    const int wid = tid >> 5;
    const int lane = tid & 31;
    const int qt = 7 - blockIdx.x;
    const int bh = blockIdx.y;
    const int b = bh >> 4, h = bh & 15;
    const int qbase = qt * 128;

    const u32 aRow = (u32)((lane & 7) + ((lane >> 3) & 1) * 8);
    const u32 aCol = (u32)(((lane >> 4) & 1) * 16);
    const u32 bRow = (u32)((lane & 7) + ((lane >> 4) & 1) * 8);
    const u32 bCol = (u32)(((lane >> 3) & 1) * 16);
    const int g  = lane >> 2;
    const int t2 = (lane & 3) * 2;

    const __nv_bfloat16* qhp = g_qhb + (size_t)b * Tt * 2048 + (size_t)h * 128;
    const __nv_bfloat16* qlp = g_qlb + (size_t)b * Tt * 2048 + (size_t)h * 128;
    const __nv_bfloat16* khp = g_khb + (size_t)b * Tt * 2048 + (size_t)h * 128;
    const __nv_bfloat16* klp = g_klb + (size_t)b * Tt * 2048 + (size_t)h * 128;
    const __nv_bfloat16* vthp = g_vth + (size_t)bh * 128 * Tt;
    const __nv_bfloat16* vtlp = g_vtl + (size_t)bh * 128 * Tt;

    for (int idx = tid; idx < 128 * 16; idx += 256) {
        int r = idx >> 4, cc = idx & 15;
        size_t gq = (size_t)(qbase + r) * 2048 + cc * 8;
        u32 so = (u32)(r * QROW + cc * 8) * 2;
        *(uint4*)(sb + QH_OFF + so) = *(const uint4*)(qhp + gq);
        *(uint4*)(sb + QL_OFF + so) = *(const uint4*)(qlp + gq);
    }
    __syncthreads();

    u32 qh[8][4], ql[8][4];
#pragma unroll
    for (int ks = 0; ks < 8; ks++) {
        u32 ra = (u32)(wid * 16 + aRow) * (QROW * 2) + (u32)ks * 32 + aCol;
        ldsm_x4(qh[ks][0], qh[ks][1], qh[ks][2], qh[ks][3], sb32 + QH_OFF + ra);
        ldsm_x4(ql[ks][0], ql[ks][1], ql[ks][2], ql[ks][3], sb32 + QL_OFF + ra);
    }
    __syncthreads();

    float o[16][4];
#pragma unroll
    for (int i = 0; i < 16; i++)
#pragma unroll
        for (int q = 0; q < 4; q++) o[i][q] = 0.f;
    float m0 = -1e30f, m1 = -1e30f, l0 = 0.f, l1 = 0.f;

    const int nkv = 2 * qt + 2;
    for (int kt = 0; kt < nkv; kt++) {
        const int kbase = kt * 64;

        for (int idx = tid; idx < 64 * 16; idx += 256) {
            int r = idx >> 4, cc = idx & 15;
            size_t gk = (size_t)(kbase + r) * 2048 + cc * 8;
            u32 so = (u32)(r * QROW + cc * 8) * 2;
            *(uint4*)(sb + KH_OFF + so) = *(const uint4*)(khp + gk);
            *(uint4*)(sb + KL_OFF + so) = *(const uint4*)(klp + gk);
        }
        for (int idx = tid; idx < 128 * 8; idx += 256) {
            int d = idx >> 3, cc = idx & 7;
            size_t gv = (size_t)d * Tt + kbase + cc * 8;
            u32 so = (u32)(d * VROW + cc * 8) * 2;
            *(uint4*)(sb + VTH_OFF + so) = *(const uint4*)(vthp + gv);
            *(uint4*)(sb + VTL_OFF + so) = *(const uint4*)(vtlp + gv);
        }
        __syncthreads();

        float sf[8][4];
#pragma unroll
        for (int i = 0; i < 8; i++)
#pragma unroll
            for (int q = 0; q < 4; q++) sf[i][q] = 0.f;

#pragma unroll
        for (int np = 0; np < 4; np++)
#pragma unroll
            for (int ks = 0; ks < 8; ks++) {
                u32 rb = (u32)(np * 16 + bRow) * (QROW * 2) + (u32)ks * 32 + bCol;
                u32 kh[4], kl[4];
                ldsm_x4(kh[0], kh[1], kh[2], kh[3], sb32 + KH_OFF + rb);
                ldsm_x4(kl[0], kl[1], kl[2], kl[3], sb32 + KL_OFF + rb);
                mma16816(sf[np * 2 + 0], qh[ks], &kh[0]);
                mma16816(sf[np * 2 + 1], qh[ks], &kh[2]);
                mma16816(sf[np * 2 + 0], ql[ks], &kh[0]);
                mma16816(sf[np * 2 + 1], ql[ks], &kh[2]);
                mma16816(sf[np * 2 + 0], qh[ks], &kl[0]);
                mma16816(sf[np * 2 + 1], qh[ks], &kl[2]);
            }

        const int row0 = qbase + wid * 16 + g;
        const int row1 = row0 + 8;
        if (kbase + 63 > qbase + wid * 16) {
#pragma unroll
            for (int nt = 0; nt < 8; nt++) {
                int col = kbase + nt * 8 + t2;
                if (col     > row0) sf[nt][0] = -1e30f;
                if (col + 1 > row0) sf[nt][1] = -1e30f;
                if (col     > row1) sf[nt][2] = -1e30f;
                if (col + 1 > row1) sf[nt][3] = -1e30f;
            }
        }

        float mx0 = -1e30f, mx1 = -1e30f;
#pragma unroll
        for (int nt = 0; nt < 8; nt++) {
            mx0 = fmaxf(mx0, fmaxf(sf[nt][0], sf[nt][1]));
            mx1 = fmaxf(mx1, fmaxf(sf[nt][2], sf[nt][3]));
        }
        mx0 = fmaxf(mx0, __shfl_xor_sync(0xffffffffu, mx0, 1));
        mx0 = fmaxf(mx0, __shfl_xor_sync(0xffffffffu, mx0, 2));
        mx1 = fmaxf(mx1, __shfl_xor_sync(0xffffffffu, mx1, 1));
        mx1 = fmaxf(mx1, __shfl_xor_sync(0xffffffffu, mx1, 2));
        float mn0 = fmaxf(m0, mx0);
        float mn1 = fmaxf(m1, mx1);
        float s0 = 0.f, s1 = 0.f;
#pragma unroll
        for (int nt = 0; nt < 8; nt++) {
            sf[nt][0] = __expf(sf[nt][0] - mn0);
            sf[nt][1] = __expf(sf[nt][1] - mn0);
            sf[nt][2] = __expf(sf[nt][2] - mn1);
            sf[nt][3] = __expf(sf[nt][3] - mn1);
            s0 += sf[nt][0] + sf[nt][1];
            s1 += sf[nt][2] + sf[nt][3];
        }
        s0 += __shfl_xor_sync(0xffffffffu, s0, 1);
        s0 += __shfl_xor_sync(0xffffffffu, s0, 2);
        s1 += __shfl_xor_sync(0xffffffffu, s1, 1);
        s1 += __shfl_xor_sync(0xffffffffu, s1, 2);
        float al0 = __expf(m0 - mn0);
        float al1 = __expf(m1 - mn1);
        l0 = l0 * al0 + s0;  m0 = mn0;
        l1 = l1 * al1 + s1;  m1 = mn1;
#pragma unroll
        for (int nt = 0; nt < 16; nt++) {
            o[nt][0] *= al0; o[nt][1] *= al0;
            o[nt][2] *= al1; o[nt][3] *= al1;
        }

        u32 ph[4][4], pl[4][4];
#pragma unroll
        for (int j = 0; j < 4; j++) {
            ph[j][0] = split2(sf[2 * j][0],     sf[2 * j][1],     pl[j][0]);
            ph[j][1] = split2(sf[2 * j][2],     sf[2 * j][3],     pl[j][1]);
            ph[j][2] = split2(sf[2 * j + 1][0], sf[2 * j + 1][1], pl[j][2]);
            ph[j][3] = split2(sf[2 * j + 1][2], sf[2 * j + 1][3], pl[j][3]);
        }

#pragma unroll
        for (int np = 0; np < 8; np++)
#pragma unroll
            for (int ks = 0; ks < 4; ks++) {
                u32 rb = (u32)(np * 16 + bRow) * (VROW * 2) + (u32)ks * 32 + bCol;
                u32 vh[4], vl[4];
                ldsm_x4(vh[0], vh[1], vh[2], vh[3], sb32 + VTH_OFF + rb);
                ldsm_x4(vl[0], vl[1], vl[2], vl[3], sb32 + VTL_OFF + rb);
                mma16816(o[np * 2 + 0], ph[ks], &vh[0]);
                mma16816(o[np * 2 + 1], ph[ks], &vh[2]);
                mma16816(o[np * 2 + 0], pl[ks], &vh[0]);
                mma16816(o[np * 2 + 1], pl[ks], &vh[2]);
                mma16816(o[np * 2 + 0], ph[ks], &vl[0]);
                mma16816(o[np * 2 + 1], ph[ks], &vl[2]);
            }
        __syncthreads();
    }

    float inv0 = 1.0f / l0;
    float inv1 = 1.0f / l1;
    __nv_bfloat16* yhp = g_yh + (size_t)b * Tt * 2048 + (size_t)h * 128;
    __nv_bfloat16* ylp = g_yl + (size_t)b * Tt * 2048 + (size_t)h * 128;
#pragma unroll
    for (int nt = 0; nt < 16; nt++) {
        int row = qbase + wid * 16 + g;
        int col = nt * 8 + t2;
        u32 lo0, lo1;
        u32 hi0 = split2(o[nt][0] * inv0, o[nt][1] * inv0, lo0);
        u32 hi1 = split2(o[nt][2] * inv1, o[nt][3] * inv1, lo1);
        *(u32*)(yhp + (size_t)row * 2048 + col)       = hi0;
        *(u32*)(ylp + (size_t)row * 2048 + col)       = lo0;
        *(u32*)(yhp + (size_t)(row + 8) * 2048 + col) = hi1;
        *(u32*)(ylp + (size_t)(row + 8) * 2048 + col) = lo1;
    }
}

// ================= launch =========================================================
extern "C" void kernel_launch(void* const* d_in, const int* in_sizes, int n_in,
                              void* d_out, int out_size)
{
    (void)in_sizes; (void)n_in; (void)out_size;
    const float* x  = (const float*)d_in[0];
    const float* Wq = (const float*)d_in[1];
    const float* Wk = (const float*)d_in[2];
    const float* Wv = (const float*)d_in[3];
    const float* Wo = (const float*)d_in[4];
    float* out = (float*)d_out;

    cudaFuncSetAttribute(flash_mma, cudaFuncAttributeMaxDynamicSharedMemorySize, FA_SMEM);
    cudaFuncSetAttribute(qkv_mma,   cudaFuncAttributeMaxDynamicSharedMemorySize, GEMM_SMEM);
    cudaFuncSetAttribute(out_mma,   cudaFuncAttributeMaxDynamicSharedMemorySize, GEMM_SMEM);

    __nv_bfloat16 *xh, *xl, *wqh, *wql, *wkh, *wkl, *wvh, *wvl, *woh, *wol;
    cudaGetSymbolAddress((void**)&xh,  g_xh);  cudaGetSymbolAddress((void**)&xl,  g_xl);
    cudaGetSymbolAddress((void**)&wqh, g_wqh); cudaGetSymbolAddress((void**)&wql, g_wql);
    cudaGetSymbolAddress((void**)&wkh, g_wkh); cudaGetSymbolAddress((void**)&wkl, g_wkl);
    cudaGetSymbolAddress((void**)&wvh, g_wvh); cudaGetSymbolAddress((void**)&wvl, g_wvl);
    cudaGetSymbolAddress((void**)&woh, g_woh); cudaGetSymbolAddress((void**)&wol, g_wol);

    const int CONV_BLKS = (BT * Cc / 4) / 256;

    cs_table_kernel<<<(Tt * 64) / 256, 256>>>();                      // 1
    conv_split<<<CONV_BLKS, 256>>>(x,  xh,  xl);                      // 2
    conv_split<<<CONV_BLKS, 256>>>(Wq, wqh, wql);                     // 3
    conv_split<<<CONV_BLKS, 256>>>(Wk, wkh, wkl);                     // 4
    conv_split2<<<dim3(CONV_BLKS, 1, 2), 256>>>(Wv, wvh, wvl,
                                                Wo, woh, wol);        // 5
    qkv_mma<<<dim3(32, 16, 3), 256, GEMM_SMEM>>>();                   // 6
    prep_qk<<<(BT * Hh * 64) / 256, 256>>>();                         // 7
    prep_vt<<<dim3(16, 32), 256>>>();                                 // 8
    flash_mma<<<dim3(8, 32), 256, FA_SMEM>>>();                       // 9
    out_mma<<<dim3(32, 16), 256, GEMM_SMEM>>>(out);                   // 10
}

// round 14
// speedup vs baseline: 1.0839x; 1.0839x over previous
#include <cuda_runtime.h>
#include <cuda_bf16.h>
#include <math.h>

#define Bb 2
#define Tt 1024
#define Cc 2048
#define Hh 16
#define Dd 128
#define BT (Bb*Tt)

typedef unsigned long long u64;
typedef unsigned int u32;

// ================= portable tensor-core helpers ===================================
__device__ __forceinline__ u32 smem_u32_of(const void* p) {
    u32 a; asm("{ .reg .u64 t; cvta.to.shared.u64 t, %1; cvt.u32.u64 %0, t; }"
               : "=r"(a) : "l"(p));
    return a;
}
__device__ __forceinline__ void ldsm_x4(u32& r0, u32& r1, u32& r2, u32& r3, u32 addr) {
    asm volatile("ldmatrix.sync.aligned.m8n8.x4.shared.b16 {%0,%1,%2,%3}, [%4];"
                 : "=r"(r0), "=r"(r1), "=r"(r2), "=r"(r3) : "r"(addr));
}
__device__ __forceinline__ void mma16816(float* c, const u32* a, const u32* b) {
    asm volatile(
        "mma.sync.aligned.m16n8k16.row.col.f32.bf16.bf16.f32 "
        "{%0,%1,%2,%3}, {%4,%5,%6,%7}, {%8,%9}, {%0,%1,%2,%3};"
        : "+f"(c[0]), "+f"(c[1]), "+f"(c[2]), "+f"(c[3])
        : "r"(a[0]), "r"(a[1]), "r"(a[2]), "r"(a[3]), "r"(b[0]), "r"(b[1]));
}
__device__ __forceinline__ u32 pack_bf2(__nv_bfloat16 x, __nv_bfloat16 y) {
    __nv_bfloat162 t; t.x = x; t.y = y;
    return *(u32*)&t;
}
__device__ __forceinline__ u32 split2(float x, float y, u32& lo) {
    __nv_bfloat16 hx = __float2bfloat16(x);
    __nv_bfloat16 hy = __float2bfloat16(y);
    lo = pack_bf2(__float2bfloat16(x - __bfloat162float(hx)),
                  __float2bfloat16(y - __bfloat162float(hy)));
    return pack_bf2(hx, hy);
}
__device__ __forceinline__ void cp16(u32 smem, const void* g) {
    asm volatile("cp.async.cg.shared.global [%0], [%1], 16;" :: "r"(smem), "l"(g));
}
#define CP_COMMIT() asm volatile("cp.async.commit_group;" ::: "memory")
#define CP_WAIT(n)  asm volatile("cp.async.wait_group %0;" :: "n"(n) : "memory")

// ================= scratch ========================================================
__device__ float g_q[BT * Cc];
__device__ float g_k[BT * Cc];
__device__ float g_v[BT * Cc];
__device__ float g_cos[Tt * 64];
__device__ float g_sin[Tt * 64];
__device__ __nv_bfloat16 g_xh[BT * Cc],  g_xl[BT * Cc];
__device__ __nv_bfloat16 g_wqh[Cc * Cc], g_wql[Cc * Cc];
__device__ __nv_bfloat16 g_wkh[Cc * Cc], g_wkl[Cc * Cc];
__device__ __nv_bfloat16 g_wvh[Cc * Cc], g_wvl[Cc * Cc];
__device__ __nv_bfloat16 g_woh[Cc * Cc], g_wol[Cc * Cc];
__device__ __nv_bfloat16 g_yh[BT * Cc],  g_yl[BT * Cc];
__device__ __nv_bfloat16 g_qhb[BT * Cc], g_qlb[BT * Cc];
__device__ __nv_bfloat16 g_khb[BT * Cc], g_klb[BT * Cc];
__device__ __nv_bfloat16 g_vth[32 * 128 * Tt], g_vtl[32 * 128 * Tt];

// ================= fp32 -> bf16 hi/lo split ======================================
__device__ __forceinline__ void split_store4(const float* src, __nv_bfloat16* hi,
                                             __nv_bfloat16* lo, int i)
{
    float4 v = *(const float4*)(src + i);
    __nv_bfloat16 h0 = __float2bfloat16(v.x);
    __nv_bfloat16 h1 = __float2bfloat16(v.y);
    __nv_bfloat16 h2 = __float2bfloat16(v.z);
    __nv_bfloat16 h3 = __float2bfloat16(v.w);
    __nv_bfloat162 H0; H0.x = h0; H0.y = h1;
    __nv_bfloat162 H1; H1.x = h2; H1.y = h3;
    *(__nv_bfloat162*)(hi + i)     = H0;
    *(__nv_bfloat162*)(hi + i + 2) = H1;
    __nv_bfloat162 L0, L1;
    L0.x = __float2bfloat16(v.x - __bfloat162float(h0));
    L0.y = __float2bfloat16(v.y - __bfloat162float(h1));
    L1.x = __float2bfloat16(v.z - __bfloat162float(h2));
    L1.y = __float2bfloat16(v.w - __bfloat162float(h3));
    *(__nv_bfloat162*)(lo + i)     = L0;
    *(__nv_bfloat162*)(lo + i + 2) = L1;
}

__global__ void __launch_bounds__(256)
conv_split(const float* __restrict__ src, __nv_bfloat16* __restrict__ hi,
           __nv_bfloat16* __restrict__ lo)
{
    int i = (blockIdx.x * blockDim.x + threadIdx.x) * 4;
    split_store4(src, hi, lo, i);
}

__global__ void __launch_bounds__(256)
conv_split2(const float* __restrict__ s0, __nv_bfloat16* __restrict__ h0,
            __nv_bfloat16* __restrict__ l0, const float* __restrict__ s1,
            __nv_bfloat16* __restrict__ h1, __nv_bfloat16* __restrict__ l1)
{
    int i = (blockIdx.x * blockDim.x + threadIdx.x) * 4;
    if (blockIdx.z == 0) split_store4(s0, h0, l0, i);
    else                 split_store4(s1, h1, l1, i);
}

// ================= HMMA split-bf16 NT GEMM (R12-verified, 128x128 tile) ===========
#define SROW 40
#define MATB (128 * SROW * 2)
#define BUFB (4 * MATB)
#define GEMM_SMEM (2 * BUFB)

__device__ __forceinline__ void mma_gemm_body(
    const __nv_bfloat16* __restrict__ Ah, const __nv_bfloat16* __restrict__ Al,
    const __nv_bfloat16* __restrict__ Bh, const __nv_bfloat16* __restrict__ Bl,
    float* __restrict__ Cout)
{
    extern __shared__ char sb[];
    const u32 sb32 = smem_u32_of(sb);

    const int tid = threadIdx.x;
    const int wid = tid >> 5;
    const int lane = tid & 31;
    const int bm = blockIdx.y * 128;
    const int bn = blockIdx.x * 128;
    const int m0 = (wid >> 1) * 32;
    const int n0 = (wid & 1) * 64;

    float c[2][8][4];
#pragma unroll
    for (int i = 0; i < 2; i++)
#pragma unroll
        for (int j = 0; j < 8; j++)
#pragma unroll
            for (int q = 0; q < 4; q++) c[i][j][q] = 0.f;

    const int lrow = tid >> 1;
    const int lhalf = (tid & 1) * 16;
    const size_t gA = (size_t)(bm + lrow) * 2048 + lhalf;
    const size_t gB = (size_t)(bn + lrow) * 2048 + lhalf;
    const u32 sOff = (u32)(lrow * (SROW * 2) + lhalf * 2);

    const u32 aRow = (u32)((lane & 7) + ((lane >> 3) & 1) * 8);
    const u32 aCol = (u32)(((lane >> 4) & 1) * 16);
    const u32 bRow = (u32)((lane & 7) + ((lane >> 4) & 1) * 8);
    const u32 bCol = (u32)(((lane >> 3) & 1) * 16);

    uint4 pf[8];
#pragma unroll
    for (int m = 0; m < 2; m++) {
        pf[0 + m] = *(const uint4*)(Ah + gA + m * 8);
        pf[2 + m] = *(const uint4*)(Al + gA + m * 8);
        pf[4 + m] = *(const uint4*)(Bh + gB + m * 8);
        pf[6 + m] = *(const uint4*)(Bl + gB + m * 8);
    }

    for (int k0 = 0; k0 < 2048; k0 += 32) {
        const u32 buf = ((u32)(k0 >> 5) & 1) * BUFB;

#pragma unroll
        for (int m = 0; m < 2; m++) {
            *(uint4*)(sb + buf + 0 * MATB + sOff + m * 16) = pf[0 + m];
            *(uint4*)(sb + buf + 1 * MATB + sOff + m * 16) = pf[2 + m];
            *(uint4*)(sb + buf + 2 * MATB + sOff + m * 16) = pf[4 + m];
            *(uint4*)(sb + buf + 3 * MATB + sOff + m * 16) = pf[6 + m];
        }
        __syncthreads();

        if (k0 + 32 < 2048) {
#pragma unroll
            for (int m = 0; m < 2; m++) {
                pf[0 + m] = *(const uint4*)(Ah + gA + k0 + 32 + m * 8);
                pf[2 + m] = *(const uint4*)(Al + gA + k0 + 32 + m * 8);
                pf[4 + m] = *(const uint4*)(Bh + gB + k0 + 32 + m * 8);
                pf[6 + m] = *(const uint4*)(Bl + gB + k0 + 32 + m * 8);
            }
        }

        const u32 baseAh = sb32 + buf;
        const u32 baseAl = baseAh + MATB;
        const u32 baseBh = baseAh + 2 * MATB;
        const u32 baseBl = baseAh + 3 * MATB;

#pragma unroll
        for (int s = 0; s < 2; s++) {
            const u32 kb = (u32)(s * 32);
            u32 ah[2][4], al[2][4], bh[4][4], bl[4][4];
#pragma unroll
            for (int mi = 0; mi < 2; mi++) {
                u32 ra = (u32)(m0 + mi * 16 + aRow) * (SROW * 2) + kb + aCol;
                ldsm_x4(ah[mi][0], ah[mi][1], ah[mi][2], ah[mi][3], baseAh + ra);
                ldsm_x4(al[mi][0], al[mi][1], al[mi][2], al[mi][3], baseAl + ra);
            }
#pragma unroll
            for (int np = 0; np < 4; np++) {
                u32 rb = (u32)(n0 + np * 16 + bRow) * (SROW * 2) + kb + bCol;
                ldsm_x4(bh[np][0], bh[np][1], bh[np][2], bh[np][3], baseBh + rb);
                ldsm_x4(bl[np][0], bl[np][1], bl[np][2], bl[np][3], baseBl + rb);
            }
#pragma unroll
            for (int mi = 0; mi < 2; mi++)
#pragma unroll
                for (int np = 0; np < 4; np++) {
                    mma16816(c[mi][np * 2 + 0], ah[mi], &bh[np][0]);
                    mma16816(c[mi][np * 2 + 1], ah[mi], &bh[np][2]);
                    mma16816(c[mi][np * 2 + 0], al[mi], &bh[np][0]);
                    mma16816(c[mi][np * 2 + 1], al[mi], &bh[np][2]);
                    mma16816(c[mi][np * 2 + 0], ah[mi], &bl[np][0]);
                    mma16816(c[mi][np * 2 + 1], ah[mi], &bl[np][2]);
                }
        }
        __syncthreads();
    }

    const int g  = lane >> 2;
    const int tg = (lane & 3) * 2;
#pragma unroll
    for (int mi = 0; mi < 2; mi++)
#pragma unroll
        for (int nj = 0; nj < 8; nj++) {
            int row = bm + m0 + mi * 16 + g;
            int col = bn + n0 + nj * 8 + tg;
            float* cp0 = Cout + (size_t)row * 2048 + col;
            float* cp1 = Cout + (size_t)(row + 8) * 2048 + col;
            *(float2*)cp0 = make_float2(c[mi][nj][0], c[mi][nj][1]);
            *(float2*)cp1 = make_float2(c[mi][nj][2], c[mi][nj][3]);
        }
}

__global__ void __launch_bounds__(256, 1)
qkv_mma()
{
    const __nv_bfloat16 *Bh, *Bl; float* out;
    if (blockIdx.z == 0)      { Bh = g_wqh; Bl = g_wql; out = g_q; }
    else if (blockIdx.z == 1) { Bh = g_wkh; Bl = g_wkl; out = g_k; }
    else                      { Bh = g_wvh; Bl = g_wvl; out = g_v; }
    mma_gemm_body(g_xh, g_xl, Bh, Bl, out);
}

__global__ void __launch_bounds__(256, 1)
out_mma(float* __restrict__ out)
{
    mma_gemm_body(g_yh, g_yl, g_woh, g_wol, out);
}

// ================= RoPE cos/sin table =============================================
__global__ void cs_table_kernel()
{
    int idx = blockIdx.x * blockDim.x + threadIdx.x;
    if (idx >= Tt * 64) return;
    int t = idx >> 6;
    int j = idx & 63;
    float invf = (float)exp(-((double)(2 * j) / 128.0) * log(10000.0));
    float thf  = (float)t * invf;
    double cd, sd;
    sincos((double)thf, &cd, &sd);
    g_cos[idx] = (float)cd;
    g_sin[idx] = (float)sd;
}

// ================= prep: rope q/k -> bf16 splits ==================================
__global__ void __launch_bounds__(256)
prep_qk()
{
    int idx = blockIdx.x * blockDim.x + threadIdx.x;
    int j   = idx & 63;
    int h   = (idx >> 6) & 15;
    int row = idx >> 10;
    int t   = row & (Tt - 1);
    const float scale = 0.08838834764831845f;

    float c = g_cos[t * 64 + j];
    float s = g_sin[t * 64 + j];
    size_t base = (size_t)row * 2048 + (size_t)h * 128 + j;

    {
        float a0 = g_q[base], a1 = g_q[base + 64];
        float r0 = (a0 * c + a1 * s) * scale;
        float r1 = (a1 * c - a0 * s) * scale;
        __nv_bfloat16 h0 = __float2bfloat16(r0);
        __nv_bfloat16 h1 = __float2bfloat16(r1);
        g_qhb[base]      = h0;
        g_qhb[base + 64] = h1;
        g_qlb[base]      = __float2bfloat16(r0 - __bfloat162float(h0));
        g_qlb[base + 64] = __float2bfloat16(r1 - __bfloat162float(h1));
    }
    {
        float a0 = g_k[base], a1 = g_k[base + 64];
        float r0 = a0 * c + a1 * s;
        float r1 = a1 * c - a0 * s;
        __nv_bfloat16 h0 = __float2bfloat16(r0);
        __nv_bfloat16 h1 = __float2bfloat16(r1);
        g_khb[base]      = h0;
        g_khb[base + 64] = h1;
        g_klb[base]      = __float2bfloat16(r0 - __bfloat162float(h0));
        g_klb[base + 64] = __float2bfloat16(r1 - __bfloat162float(h1));
    }
}

// ================= prep: transpose V -> [bh][d=128][t] bf16 splits ================
__global__ void __launch_bounds__(256)
prep_vt()
{
    __shared__ float vs[128][65];
    const int tid = threadIdx.x;
    const int tt = blockIdx.x;
    const int bh = blockIdx.y;
    const int b = bh >> 4, h = bh & 15;
    const int tb = tt * 64;

    const float* vp = g_v + (size_t)b * Tt * Cc + (size_t)h * Dd;
    for (int e = tid; e < 64 * 128; e += 256) {
        int t = e >> 7, d = e & 127;
        vs[d][t] = vp[(size_t)(tb + t) * 2048 + d];
    }
    __syncthreads();

    __nv_bfloat16* oh = g_vth + (size_t)bh * 128 * Tt + tb;
    __nv_bfloat16* ol = g_vtl + (size_t)bh * 128 * Tt + tb;
    for (int e = tid; e < 128 * 32; e += 256) {
        int d = e >> 5, tw = (e & 31) * 2;
        float v0 = vs[d][tw], v1 = vs[d][tw + 1];
        u32 lo;
        u32 hi = split2(v0, v1, lo);
        *(u32*)(oh + (size_t)d * Tt + tw) = hi;
        *(u32*)(ol + (size_t)d * Tt + tw) = lo;
    }
}

// ================= HMMA flash attention, double-buffered cp.async K/V =============
#define QROW 136
#define VROW 72
// per-KV-buffer internal offsets
#define KB_KH 0
#define KB_KL (64 * QROW * 2)                 // 17408
#define KB_VH (2 * 64 * QROW * 2)             // 34816
#define KB_VL (KB_VH + 128 * VROW * 2)        // 53248
#define KVBUF (KB_VL + 128 * VROW * 2)        // 71680
// Q staging overlaps buffer 0 (consumed into registers before pipeline starts)
#define QH_OFF 0
#define QL_OFF (128 * QROW * 2)               // 34816; Q total 69632 < KVBUF
#define FA_SMEM (2 * KVBUF)                   // 143360

__device__ __forceinline__ void fa_stage(
    char* dst, const __nv_bfloat16* khp, const __nv_bfloat16* klp,
    const __nv_bfloat16* vthp, const __nv_bfloat16* vtlp, int kbase, int tid)
{
    const u32 d32 = smem_u32_of(dst);
#pragma unroll
    for (int it = 0; it < 4; it++) {
        int idx = tid + it * 256;             // 0..1023
        int r = idx >> 4, cc = idx & 15;
        size_t gk = (size_t)(kbase + r) * 2048 + cc * 8;
        u32 so = (u32)(r * QROW + cc * 8) * 2;
        cp16(d32 + KB_KH + so, khp + gk);
        cp16(d32 + KB_KL + so, klp + gk);
    }
#pragma unroll
    for (int it = 0; it < 4; it++) {
        int idx = tid + it * 256;             // 0..1023
        int d = idx >> 3, cc = idx & 7;
        size_t gv = (size_t)d * Tt + kbase + cc * 8;
        u32 so = (u32)(d * VROW + cc * 8) * 2;
        cp16(d32 + KB_VH + so, vthp + gv);
        cp16(d32 + KB_VL + so, vtlp + gv);
    }
}

__global__ void __launch_bounds__(256, 1)
flash_mma()
{
    extern __shared__ char sb[];
    const u32 sb32 = smem_u32_of(sb);

    const int tid = threadIdx.x;
    const int wid = tid >> 5;
    const int lane = tid & 31;
    const int qt = 7 - blockIdx.x;
    const int bh = blockIdx.y;
    const int b = bh >> 4, h = bh & 15;
    const int qbase = qt * 128;

    const u32 aRow = (u32)((lane & 7) + ((lane >> 3) & 1) * 8);
    const u32 aCol = (u32)(((lane >> 4) & 1) * 16);
    const u32 bRow = (u32)((lane & 7) + ((lane >> 4) & 1) * 8);
    const u32 bCol = (u32)(((lane >> 3) & 1) * 16);
    const int g  = lane >> 2;
    const int t2 = (lane & 3) * 2;

    const __nv_bfloat16* qhp = g_qhb + (size_t)b * Tt * 2048 + (size_t)h * 128;
    const __nv_bfloat16* qlp = g_qlb + (size_t)b * Tt * 2048 + (size_t)h * 128;
    const __nv_bfloat16* khp = g_khb + (size_t)b * Tt * 2048 + (size_t)h * 128;
    const __nv_bfloat16* klp = g_klb + (size_t)b * Tt * 2048 + (size_t)h * 128;
    const __nv_bfloat16* vthp = g_vth + (size_t)bh * 128 * Tt;
    const __nv_bfloat16* vtlp = g_vtl + (size_t)bh * 128 * Tt;

    // ---- stage Q (sync copies into buffer-0 region), load fragments --------------
    for (int idx = tid; idx < 128 * 16; idx += 256) {
        int r = idx >> 4, cc = idx & 15;
        size_t gq = (size_t)(qbase + r) * 2048 + cc * 8;
        u32 so = (u32)(r * QROW + cc * 8) * 2;
        *(uint4*)(sb + QH_OFF + so) = *(const uint4*)(qhp + gq);
        *(uint4*)(sb + QL_OFF + so) = *(const uint4*)(qlp + gq);
    }
    __syncthreads();

    u32 qh[8][4], ql[8][4];
#pragma unroll
    for (int ks = 0; ks < 8; ks++) {
        u32 ra = (u32)(wid * 16 + aRow) * (QROW * 2) + (u32)ks * 32 + aCol;
        ldsm_x4(qh[ks][0], qh[ks][1], qh[ks][2], qh[ks][3], sb32 + QH_OFF + ra);
        ldsm_x4(ql[ks][0], ql[ks][1], ql[ks][2], ql[ks][3], sb32 + QL_OFF + ra);
    }
    __syncthreads();   // Q region reused as KV buffer 0

    float o[16][4];
#pragma unroll
    for (int i = 0; i < 16; i++)
#pragma unroll
        for (int q = 0; q < 4; q++) o[i][q] = 0.f;
    float m0 = -1e30f, m1 = -1e30f, l0 = 0.f, l1 = 0.f;

    const int nkv = 2 * qt + 2;

    // pipeline prologue
    fa_stage(sb, khp, klp, vthp, vtlp, 0, tid);
    CP_COMMIT();

    for (int kt = 0; kt < nkv; kt++) {
        const int kbase = kt * 64;

        if (kt + 1 < nkv)
            fa_stage(sb + ((kt + 1) & 1) * KVBUF, khp, klp, vthp, vtlp,
                     (kt + 1) * 64, tid);
        CP_COMMIT();
        CP_WAIT(1);            // buffer for kt complete
        __syncthreads();

        const u32 base = sb32 + (u32)(kt & 1) * KVBUF;

        // S = Q K^T (3-term split)
        float sf[8][4];
#pragma unroll
        for (int i = 0; i < 8; i++)
#pragma unroll
            for (int q = 0; q < 4; q++) sf[i][q] = 0.f;

#pragma unroll
        for (int np = 0; np < 4; np++)
#pragma unroll
            for (int ks = 0; ks < 8; ks++) {
                u32 rb = (u32)(np * 16 + bRow) * (QROW * 2) + (u32)ks * 32 + bCol;
                u32 kh[4], kl[4];
                ldsm_x4(kh[0], kh[1], kh[2], kh[3], base + KB_KH + rb);
                ldsm_x4(kl[0], kl[1], kl[2], kl[3], base + KB_KL + rb);
                mma16816(sf[np * 2 + 0], qh[ks], &kh[0]);
                mma16816(sf[np * 2 + 1], qh[ks], &kh[2]);
                mma16816(sf[np * 2 + 0], ql[ks], &kh[0]);
                mma16816(sf[np * 2 + 1], ql[ks], &kh[2]);
                mma16816(sf[np * 2 + 0], qh[ks], &kl[0]);
                mma16816(sf[np * 2 + 1], qh[ks], &kl[2]);
            }

        // causal mask
        const int row0 = qbase + wid * 16 + g;
        const int row1 = row0 + 8;
        if (kbase + 63 > qbase + wid * 16) {
#pragma unroll
            for (int nt = 0; nt < 8; nt++) {
                int col = kbase + nt * 8 + t2;
                if (col     > row0) sf[nt][0] = -1e30f;
                if (col + 1 > row0) sf[nt][1] = -1e30f;
                if (col     > row1) sf[nt][2] = -1e30f;
                if (col + 1 > row1) sf[nt][3] = -1e30f;
            }
        }

        // online softmax
        float mx0 = -1e30f, mx1 = -1e30f;
#pragma unroll
        for (int nt = 0; nt < 8; nt++) {
            mx0 = fmaxf(mx0, fmaxf(sf[nt][0], sf[nt][1]));
            mx1 = fmaxf(mx1, fmaxf(sf[nt][2], sf[nt][3]));
        }
        mx0 = fmaxf(mx0, __shfl_xor_sync(0xffffffffu, mx0, 1));
        mx0 = fmaxf(mx0, __shfl_xor_sync(0xffffffffu, mx0, 2));
        mx1 = fmaxf(mx1, __shfl_xor_sync(0xffffffffu, mx1, 1));
        mx1 = fmaxf(mx1, __shfl_xor_sync(0xffffffffu, mx1, 2));
        float mn0 = fmaxf(m0, mx0);
        float mn1 = fmaxf(m1, mx1);
        float s0 = 0.f, s1 = 0.f;
#pragma unroll
        for (int nt = 0; nt < 8; nt++) {
            sf[nt][0] = __expf(sf[nt][0] - mn0);
            sf[nt][1] = __expf(sf[nt][1] - mn0);
            sf[nt][2] = __expf(sf[nt][2] - mn1);
            sf[nt][3] = __expf(sf[nt][3] - mn1);
            s0 += sf[nt][0] + sf[nt][1];
            s1 += sf[nt][2] + sf[nt][3];
        }
        s0 += __shfl_xor_sync(0xffffffffu, s0, 1);
        s0 += __shfl_xor_sync(0xffffffffu, s0, 2);
        s1 += __shfl_xor_sync(0xffffffffu, s1, 1);
        s1 += __shfl_xor_sync(0xffffffffu, s1, 2);
        float al0 = __expf(m0 - mn0);
        float al1 = __expf(m1 - mn1);
        l0 = l0 * al0 + s0;  m0 = mn0;
        l1 = l1 * al1 + s1;  m1 = mn1;
#pragma unroll
        for (int nt = 0; nt < 16; nt++) {
            o[nt][0] *= al0; o[nt][1] *= al0;
            o[nt][2] *= al1; o[nt][3] *= al1;
        }

        // P fragments in-register
        u32 ph[4][4], pl[4][4];
#pragma unroll
        for (int j = 0; j < 4; j++) {
            ph[j][0] = split2(sf[2 * j][0],     sf[2 * j][1],     pl[j][0]);
            ph[j][1] = split2(sf[2 * j][2],     sf[2 * j][3],     pl[j][1]);
            ph[j][2] = split2(sf[2 * j + 1][0], sf[2 * j + 1][1], pl[j][2]);
            ph[j][3] = split2(sf[2 * j + 1][2], sf[2 * j + 1][3], pl[j][3]);
        }

        // O += P V  (3-term split)
#pragma unroll
        for (int np = 0; np < 8; np++)
#pragma unroll
            for (int ks = 0; ks < 4; ks++) {
                u32 rb = (u32)(np * 16 + bRow) * (VROW * 2) + (u32)ks * 32 + bCol;
                u32 vh[4], vl[4];
                ldsm_x4(vh[0], vh[1], vh[2], vh[3], base + KB_VH + rb);
                ldsm_x4(vl[0], vl[1], vl[2], vl[3], base + KB_VL + rb);
                mma16816(o[np * 2 + 0], ph[ks], &vh[0]);
                mma16816(o[np * 2 + 1], ph[ks], &vh[2]);
                mma16816(o[np * 2 + 0], pl[ks], &vh[0]);
                mma16816(o[np * 2 + 1], pl[ks], &vh[2]);
                mma16816(o[np * 2 + 0], ph[ks], &vl[0]);
                mma16816(o[np * 2 + 1], ph[ks], &vl[2]);
            }
        __syncthreads();   // all reads of this buffer done before it is re-staged
    }

    float inv0 = 1.0f / l0;
    float inv1 = 1.0f / l1;
    __nv_bfloat16* yhp = g_yh + (size_t)b * Tt * 2048 + (size_t)h * 128;
    __nv_bfloat16* ylp = g_yl + (size_t)b * Tt * 2048 + (size_t)h * 128;
#pragma unroll
    for (int nt = 0; nt < 16; nt++) {
        int row = qbase + wid * 16 + g;
        int col = nt * 8 + t2;
        u32 lo0, lo1;
        u32 hi0 = split2(o[nt][0] * inv0, o[nt][1] * inv0, lo0);
        u32 hi1 = split2(o[nt][2] * inv1, o[nt][3] * inv1, lo1);
        *(u32*)(yhp + (size_t)row * 2048 + col)       = hi0;
        *(u32*)(ylp + (size_t)row * 2048 + col)       = lo0;
        *(u32*)(yhp + (size_t)(row + 8) * 2048 + col) = hi1;
        *(u32*)(ylp + (size_t)(row + 8) * 2048 + col) = lo1;
    }
}

// ================= launch =========================================================
extern "C" void kernel_launch(void* const* d_in, const int* in_sizes, int n_in,
                              void* d_out, int out_size)
{
    (void)in_sizes; (void)n_in; (void)out_size;
    const float* x  = (const float*)d_in[0];
    const float* Wq = (const float*)d_in[1];
    const float* Wk = (const float*)d_in[2];
    const float* Wv = (const float*)d_in[3];
    const float* Wo = (const float*)d_in[4];
    float* out = (float*)d_out;

    cudaFuncSetAttribute(flash_mma, cudaFuncAttributeMaxDynamicSharedMemorySize, FA_SMEM);
    cudaFuncSetAttribute(qkv_mma,   cudaFuncAttributeMaxDynamicSharedMemorySize, GEMM_SMEM);
    cudaFuncSetAttribute(out_mma,   cudaFuncAttributeMaxDynamicSharedMemorySize, GEMM_SMEM);

    __nv_bfloat16 *xh, *xl, *wqh, *wql, *wkh, *wkl, *wvh, *wvl, *woh, *wol;
    cudaGetSymbolAddress((void**)&xh,  g_xh);  cudaGetSymbolAddress((void**)&xl,  g_xl);
    cudaGetSymbolAddress((void**)&wqh, g_wqh); cudaGetSymbolAddress((void**)&wql, g_wql);
    cudaGetSymbolAddress((void**)&wkh, g_wkh); cudaGetSymbolAddress((void**)&wkl, g_wkl);
    cudaGetSymbolAddress((void**)&wvh, g_wvh); cudaGetSymbolAddress((void**)&wvl, g_wvl);
    cudaGetSymbolAddress((void**)&woh, g_woh); cudaGetSymbolAddress((void**)&wol, g_wol);

    const int CONV_BLKS = (BT * Cc / 4) / 256;

    cs_table_kernel<<<(Tt * 64) / 256, 256>>>();                      // 1
    conv_split<<<CONV_BLKS, 256>>>(x,  xh,  xl);                      // 2
    conv_split<<<CONV_BLKS, 256>>>(Wq, wqh, wql);                     // 3
    conv_split<<<CONV_BLKS, 256>>>(Wk, wkh, wkl);                     // 4
    conv_split2<<<dim3(CONV_BLKS, 1, 2), 256>>>(Wv, wvh, wvl,
                                                Wo, woh, wol);        // 5
    qkv_mma<<<dim3(16, 16, 3), 256, GEMM_SMEM>>>();                   // 6
    prep_qk<<<(BT * Hh * 64) / 256, 256>>>();                         // 7
    prep_vt<<<dim3(16, 32), 256>>>();                                 // 8
    flash_mma<<<dim3(8, 32), 256, FA_SMEM>>>();                       // 9
    out_mma<<<dim3(16, 16), 256, GEMM_SMEM>>>(out);                   // 10
}